// round 1
// baseline (speedup 1.0000x reference)
#include <cuda_runtime.h>
#include <math.h>

#define EMBED 1024
#define NHEAD 16
#define HDIM  64
#define BATCH 2
#define SEQ   2048
#define MROWS (BATCH*SEQ)   // 4096

// Scratch (allocation-free rule: __device__ globals)
__device__ float g_Qh[MROWS*EMBED];
__device__ float g_Kh[MROWS*EMBED];
__device__ float g_Vh[MROWS*EMBED];
__device__ float g_Y [MROWS*EMBED];

// ---------------------------------------------------------------------------
// GEMM: C[M,N] = relu(A[M,K] @ B[K,N] + bias[N])
// 128x128 tile, BK=8, 256 threads, 8x8 per-thread microtile.
// ---------------------------------------------------------------------------
__global__ __launch_bounds__(256) void gemm_bias_relu(
    const float* __restrict__ A, const float* __restrict__ B,
    const float* __restrict__ bias, float* __restrict__ C) {
  const int N = EMBED, K = EMBED;
  __shared__ float As[8][132];   // padded: conflict-free strided stores
  __shared__ float Bs[8][128];

  int tid  = threadIdx.x;
  int brow = blockIdx.y * 128;
  int bcol = blockIdx.x * 128;
  int tx = tid & 15, ty = tid >> 4;

  float acc[8][8];
  #pragma unroll
  for (int i = 0; i < 8; i++)
    #pragma unroll
    for (int j = 0; j < 8; j++) acc[i][j] = 0.f;

  int aRow = tid >> 1,  aCol = (tid & 1) * 4;
  int bRow = tid >> 5,  bCol = (tid & 31) * 4;
  const float* Aptr = A + (size_t)(brow + aRow) * K + aCol;
  const float* Bptr = B + (size_t)bRow * N + bcol + bCol;

  for (int k0 = 0; k0 < K; k0 += 8) {
    float4 av = *(const float4*)(Aptr + k0);
    float4 bv = *(const float4*)(Bptr + (size_t)k0 * N);
    As[aCol+0][aRow] = av.x; As[aCol+1][aRow] = av.y;
    As[aCol+2][aRow] = av.z; As[aCol+3][aRow] = av.w;
    *(float4*)&Bs[bRow][bCol] = bv;
    __syncthreads();
    #pragma unroll
    for (int k = 0; k < 8; k++) {
      float a[8], b[8];
      #pragma unroll
      for (int i = 0; i < 8; i++) a[i] = As[k][ty*8 + i];
      #pragma unroll
      for (int j = 0; j < 8; j++) b[j] = Bs[k][tx*8 + j];
      #pragma unroll
      for (int i = 0; i < 8; i++)
        #pragma unroll
        for (int j = 0; j < 8; j++) acc[i][j] = fmaf(a[i], b[j], acc[i][j]);
    }
    __syncthreads();
  }

  #pragma unroll
  for (int i = 0; i < 8; i++) {
    int row = brow + ty*8 + i;
    #pragma unroll
    for (int j = 0; j < 8; j += 4) {
      int col = bcol + tx*8 + j;
      float4 o;
      o.x = fmaxf(acc[i][j+0] + bias[col+0], 0.f);
      o.y = fmaxf(acc[i][j+1] + bias[col+1], 0.f);
      o.z = fmaxf(acc[i][j+2] + bias[col+2], 0.f);
      o.w = fmaxf(acc[i][j+3] + bias[col+3], 0.f);
      *(float4*)&C[(size_t)row * N + col] = o;
    }
  }
}

// ---------------------------------------------------------------------------
// Flash attention, fp32, causal. One block = one (b,h) x 64-query tile.
// 256 threads as 16x16; S-gemm: thread (ty,tx) owns rows ty*4+i, cols tx*4+j.
// PV-gemm/O: thread owns rows ty*4+i, O columns tx + 16*j (conflict-free Vs
// reads, coalesced O stores).
// ---------------------------------------------------------------------------
__global__ __launch_bounds__(256) void attn_kernel(
    const float* __restrict__ Q, const float* __restrict__ K,
    const float* __restrict__ V, float* __restrict__ O) {
  extern __shared__ float sm[];
  float (*Qs)[65] = (float(*)[65])(sm);
  float (*Ks)[65] = (float(*)[65])(sm + 64*65);
  float (*Vs)[65] = (float(*)[65])(sm + 2*64*65);
  float (*Ps)[65] = (float(*)[65])(sm + 3*64*65);

  int tid = threadIdx.x;
  int tx = tid & 15, ty = tid >> 4;
  int qt = blockIdx.x;           // query tile
  int bh = blockIdx.y;
  int b = bh >> 4, h = bh & 15;
  int q0 = qt * 64;

  const float* Qb = Q + (size_t)b * SEQ * EMBED + h * HDIM;
  const float* Kb = K + (size_t)b * SEQ * EMBED + h * HDIM;
  const float* Vb = V + (size_t)b * SEQ * EMBED + h * HDIM;

  // Load Q tile: each thread 16 floats (4x float4)
  {
    int r = tid >> 2;
    int c = (tid & 3) * 16;
    const float* src = Qb + (size_t)(q0 + r) * EMBED + c;
    #pragma unroll
    for (int u = 0; u < 4; u++) {
      float4 v4 = *(const float4*)(src + u*4);
      Qs[r][c+u*4+0] = v4.x; Qs[r][c+u*4+1] = v4.y;
      Qs[r][c+u*4+2] = v4.z; Qs[r][c+u*4+3] = v4.w;
    }
  }

  float m[4], l[4], acc[4][4];
  #pragma unroll
  for (int i = 0; i < 4; i++) {
    m[i] = -1e30f; l[i] = 0.f;
    #pragma unroll
    for (int j = 0; j < 4; j++) acc[i][j] = 0.f;
  }
  const float scale = 0.125f;  // 1/sqrt(64)

  for (int t = 0; t <= qt; t++) {
    int k0t = t * 64;
    __syncthreads();  // protect Ks/Vs/Ps against prior-iteration readers
    {
      int r = tid >> 2;
      int c = (tid & 3) * 16;
      const float* ks = Kb + (size_t)(k0t + r) * EMBED + c;
      const float* vs = Vb + (size_t)(k0t + r) * EMBED + c;
      #pragma unroll
      for (int u = 0; u < 4; u++) {
        float4 kv = *(const float4*)(ks + u*4);
        Ks[r][c+u*4+0] = kv.x; Ks[r][c+u*4+1] = kv.y;
        Ks[r][c+u*4+2] = kv.z; Ks[r][c+u*4+3] = kv.w;
        float4 vv = *(const float4*)(vs + u*4);
        Vs[r][c+u*4+0] = vv.x; Vs[r][c+u*4+1] = vv.y;
        Vs[r][c+u*4+2] = vv.z; Vs[r][c+u*4+3] = vv.w;
      }
    }
    __syncthreads();

    // S = Q K^T
    float s[4][4];
    #pragma unroll
    for (int i = 0; i < 4; i++)
      #pragma unroll
      for (int j = 0; j < 4; j++) s[i][j] = 0.f;
    #pragma unroll 8
    for (int k = 0; k < 64; k++) {
      float a[4], bb[4];
      #pragma unroll
      for (int i = 0; i < 4; i++) a[i]  = Qs[ty*4 + i][k];
      #pragma unroll
      for (int j = 0; j < 4; j++) bb[j] = Ks[tx*4 + j][k];
      #pragma unroll
      for (int i = 0; i < 4; i++)
        #pragma unroll
        for (int j = 0; j < 4; j++) s[i][j] = fmaf(a[i], bb[j], s[i][j]);
    }

    // scale + causal mask (reference uses -1e9 sentinel; exp underflows to 0)
    #pragma unroll
    for (int i = 0; i < 4; i++) {
      int qi = q0 + ty*4 + i;
      #pragma unroll
      for (int j = 0; j < 4; j++) {
        int kj = k0t + tx*4 + j;
        s[i][j] = (kj <= qi) ? s[i][j] * scale : -1e9f;
      }
    }

    // online softmax; row groups are 16 consecutive lanes (same ty)
    #pragma unroll
    for (int i = 0; i < 4; i++) {
      float mloc = fmaxf(fmaxf(s[i][0], s[i][1]), fmaxf(s[i][2], s[i][3]));
      #pragma unroll
      for (int off = 1; off < 16; off <<= 1)
        mloc = fmaxf(mloc, __shfl_xor_sync(0xffffffffu, mloc, off));
      float mnew  = fmaxf(m[i], mloc);
      float alpha = __expf(m[i] - mnew);
      float lloc = 0.f;
      #pragma unroll
      for (int j = 0; j < 4; j++) {
        s[i][j] = __expf(s[i][j] - mnew);
        lloc += s[i][j];
      }
      #pragma unroll
      for (int off = 1; off < 16; off <<= 1)
        lloc += __shfl_xor_sync(0xffffffffu, lloc, off);
      l[i] = l[i] * alpha + lloc;
      m[i] = mnew;
      #pragma unroll
      for (int j = 0; j < 4; j++) acc[i][j] *= alpha;
      #pragma unroll
      for (int j = 0; j < 4; j++) Ps[ty*4 + i][tx*4 + j] = s[i][j];
    }
    __syncthreads();

    // O += P @ V  (O cols = tx + 16*j)
    #pragma unroll 8
    for (int k = 0; k < 64; k++) {
      float p[4], vv[4];
      #pragma unroll
      for (int i = 0; i < 4; i++) p[i]  = Ps[ty*4 + i][k];
      #pragma unroll
      for (int j = 0; j < 4; j++) vv[j] = Vs[k][tx + 16*j];
      #pragma unroll
      for (int i = 0; i < 4; i++)
        #pragma unroll
        for (int j = 0; j < 4; j++) acc[i][j] = fmaf(p[i], vv[j], acc[i][j]);
    }
  }

  float* Ob = O + (size_t)b * SEQ * EMBED + h * HDIM;
  #pragma unroll
  for (int i = 0; i < 4; i++) {
    int r = q0 + ty*4 + i;
    float inv = 1.f / l[i];
    #pragma unroll
    for (int j = 0; j < 4; j++)
      Ob[(size_t)r * EMBED + tx + 16*j] = acc[i][j] * inv;
  }
}

// ---------------------------------------------------------------------------
extern "C" void kernel_launch(void* const* d_in, const int* in_sizes, int n_in,
                              void* d_out, int out_size) {
  (void)in_sizes; (void)n_in; (void)out_size;
  const float* q  = (const float*)d_in[0];
  const float* k  = (const float*)d_in[1];
  const float* v  = (const float*)d_in[2];
  // d_in[3] = mask (int32 tril) — causal structure is known, unused
  const float* Wq = (const float*)d_in[4];
  const float* bq = (const float*)d_in[5];
  const float* Wk = (const float*)d_in[6];
  const float* bk = (const float*)d_in[7];
  const float* Wv = (const float*)d_in[8];
  const float* bv = (const float*)d_in[9];
  const float* Wo = (const float*)d_in[10];
  const float* bo = (const float*)d_in[11];
  float* out = (float*)d_out;

  float *Qh, *Kh, *Vh, *Y;
  cudaGetSymbolAddress((void**)&Qh, g_Qh);
  cudaGetSymbolAddress((void**)&Kh, g_Kh);
  cudaGetSymbolAddress((void**)&Vh, g_Vh);
  cudaGetSymbolAddress((void**)&Y,  g_Y);

  dim3 ggrid(EMBED/128, MROWS/128);   // (8, 32)
  gemm_bias_relu<<<ggrid, 256>>>(q, Wq, bq, Qh);
  gemm_bias_relu<<<ggrid, 256>>>(k, Wk, bk, Kh);
  gemm_bias_relu<<<ggrid, 256>>>(v, Wv, bv, Vh);

  const int attn_smem = 4 * 64 * 65 * sizeof(float);  // 66560 B
  cudaFuncSetAttribute(attn_kernel,
                       cudaFuncAttributeMaxDynamicSharedMemorySize, attn_smem);
  dim3 agrid(SEQ/64, BATCH*NHEAD);    // (32, 32)
  attn_kernel<<<agrid, 256, attn_smem>>>(Qh, Kh, Vh, Y);

  gemm_bias_relu<<<ggrid, 256>>>(Y, Wo, bo, out);
}

// round 5
// speedup vs baseline: 1.4364x; 1.4364x over previous
#include <cuda_runtime.h>
#include <cstdint>
#include <math.h>

#define EMBED 1024
#define NHEAD 16
#define HDIM  64
#define BATCH 2
#define SEQ   2048
#define MROWS (BATCH*SEQ)   // 4096

// Scratch (allocation-free rule: __device__ globals)
__device__ float g_Qh[MROWS*EMBED];
__device__ float g_Kh[MROWS*EMBED];
__device__ float g_Vh[MROWS*EMBED];
__device__ float g_Y [MROWS*EMBED];
__device__ float g_Wt[4*EMBED*EMBED];   // N-major weights, tf32-rounded bits

__device__ __forceinline__ uint32_t f2tf32(float x) {
  uint32_t r;
  asm("cvt.rna.tf32.f32 %0, %1;" : "=r"(r) : "f"(x));
  return r;
}

__device__ __forceinline__ void mma_tf32(float c[4], const uint32_t a[4],
                                         const uint32_t b[2]) {
  asm volatile(
      "mma.sync.aligned.m16n8k8.row.col.f32.tf32.tf32.f32 "
      "{%0,%1,%2,%3},{%4,%5,%6,%7},{%8,%9},{%0,%1,%2,%3};"
      : "+f"(c[0]), "+f"(c[1]), "+f"(c[2]), "+f"(c[3])
      : "r"(a[0]), "r"(a[1]), "r"(a[2]), "r"(a[3]), "r"(b[0]), "r"(b[1]));
}

// ---------------------------------------------------------------------------
// Weight transpose: Wt[n][k] = rna_tf32(W[k][n])  (N-major, pre-rounded)
// ---------------------------------------------------------------------------
__global__ __launch_bounds__(256) void transpose_w(
    const float* __restrict__ W0, const float* __restrict__ W1,
    const float* __restrict__ W2, const float* __restrict__ W3,
    float* __restrict__ Out) {
  const float* W = (blockIdx.z == 0) ? W0 : (blockIdx.z == 1) ? W1
                 : (blockIdx.z == 2) ? W2 : W3;
  float* O = Out + (size_t)blockIdx.z * EMBED * EMBED;
  __shared__ float t[32][33];
  int tx = threadIdx.x, ty = threadIdx.y;          // 32 x 8
  int x0 = blockIdx.x * 32, y0 = blockIdx.y * 32;  // x=n, y=k
  #pragma unroll
  for (int i = 0; i < 4; i++)
    t[ty + 8*i][tx] = W[(size_t)(y0 + ty + 8*i) * EMBED + x0 + tx];
  __syncthreads();
  #pragma unroll
  for (int i = 0; i < 4; i++) {
    uint32_t r = f2tf32(t[tx][ty + 8*i]);
    *(uint32_t*)&O[(size_t)(x0 + ty + 8*i) * EMBED + y0 + tx] = r;
  }
}

// ---------------------------------------------------------------------------
// tf32 mma.sync GEMM: C[128x128] = relu(A[M,K] @ Bt[N,K]^T + bias)
// 256 threads = 8 warps (4m x 2n); warp tile 32x64 = 2 x 8 m16n8k8 tiles.
// ---------------------------------------------------------------------------
struct GemmArgs {
  const float* A; const float* B; const float* bias; float* C;
};

#define BK  32
#define LDS_W (BK + 4)   // pad 4 floats: conflict-free fragment reads

__global__ __launch_bounds__(256) void gemm_mma(GemmArgs g0, GemmArgs g1, GemmArgs g2) {
  GemmArgs g = (blockIdx.z == 0) ? g0 : (blockIdx.z == 1) ? g1 : g2;
  __shared__ float As[128][LDS_W];
  __shared__ float Bs[128][LDS_W];

  int tid = threadIdx.x;
  int wid = tid >> 5, lid = tid & 31;
  int gid = lid >> 2, tig = lid & 3;    // mma fragment coords
  int wm = wid >> 1, wn = wid & 1;      // warp grid 4 x 2
  int m0 = blockIdx.y * 128, n0 = blockIdx.x * 128;

  const float* Arow = g.A + (size_t)m0 * EMBED;
  const float* Brow = g.B + (size_t)n0 * EMBED;

  float acc[2][8][4];
  #pragma unroll
  for (int mt = 0; mt < 2; mt++)
    #pragma unroll
    for (int nt = 0; nt < 8; nt++)
      #pragma unroll
      for (int c = 0; c < 4; c++) acc[mt][nt][c] = 0.f;

  for (int kt = 0; kt < EMBED / BK; kt++) {
    int k0 = kt * BK;
    // Load 128x32 A (cvt to tf32) + 128x32 B (pre-rounded) into smem.
    #pragma unroll
    for (int i = 0; i < 4; i++) {
      int idx = tid + i * 256;          // 1024 float4 slots
      int row = idx >> 3, c4 = idx & 7; // 8 float4 per 32-float row
      float4 av = *(const float4*)(Arow + (size_t)row * EMBED + k0 + c4 * 4);
      float4 at;
      at.x = __uint_as_float(f2tf32(av.x));
      at.y = __uint_as_float(f2tf32(av.y));
      at.z = __uint_as_float(f2tf32(av.z));
      at.w = __uint_as_float(f2tf32(av.w));
      *(float4*)&As[row][c4 * 4] = at;
      *(float4*)&Bs[row][c4 * 4] =
          *(const float4*)(Brow + (size_t)row * EMBED + k0 + c4 * 4);
    }
    __syncthreads();

    #pragma unroll
    for (int ks = 0; ks < BK / 8; ks++) {
      int kb = ks * 8;
      uint32_t a[2][4], b[8][2];
      #pragma unroll
      for (int mt = 0; mt < 2; mt++) {
        int r0 = wm * 32 + mt * 16 + gid;
        a[mt][0] = __float_as_uint(As[r0    ][kb + tig]);
        a[mt][1] = __float_as_uint(As[r0 + 8][kb + tig]);
        a[mt][2] = __float_as_uint(As[r0    ][kb + tig + 4]);
        a[mt][3] = __float_as_uint(As[r0 + 8][kb + tig + 4]);
      }
      #pragma unroll
      for (int nt = 0; nt < 8; nt++) {
        int c0 = wn * 64 + nt * 8 + gid;
        b[nt][0] = __float_as_uint(Bs[c0][kb + tig]);
        b[nt][1] = __float_as_uint(Bs[c0][kb + tig + 4]);
      }
      #pragma unroll
      for (int mt = 0; mt < 2; mt++)
        #pragma unroll
        for (int nt = 0; nt < 8; nt++)
          mma_tf32(acc[mt][nt], a[mt], b[nt]);
    }
    __syncthreads();
  }

  // Epilogue: bias + relu, float2 stores.
  #pragma unroll
  for (int mt = 0; mt < 2; mt++) {
    int row = m0 + wm * 32 + mt * 16 + gid;
    #pragma unroll
    for (int nt = 0; nt < 8; nt++) {
      int col = n0 + wn * 64 + nt * 8 + tig * 2;
      float b0 = g.bias[col], b1 = g.bias[col + 1];
      float2 o0, o1;
      o0.x = fmaxf(acc[mt][nt][0] + b0, 0.f);
      o0.y = fmaxf(acc[mt][nt][1] + b1, 0.f);
      o1.x = fmaxf(acc[mt][nt][2] + b0, 0.f);
      o1.y = fmaxf(acc[mt][nt][3] + b1, 0.f);
      *(float2*)&g.C[(size_t)row * EMBED + col] = o0;
      *(float2*)&g.C[(size_t)(row + 8) * EMBED + col] = o1;
    }
  }
}

// ---------------------------------------------------------------------------
// Flash attention, fp32, causal. Heavy query-tiles first.
// ---------------------------------------------------------------------------
__global__ __launch_bounds__(256) void attn_kernel(
    const float* __restrict__ Q, const float* __restrict__ K,
    const float* __restrict__ V, float* __restrict__ O) {
  extern __shared__ float sm[];
  float (*Qs)[65] = (float(*)[65])(sm);
  float (*Ks)[65] = (float(*)[65])(sm + 64*65);
  float (*Vs)[65] = (float(*)[65])(sm + 2*64*65);
  float (*Ps)[65] = (float(*)[65])(sm + 3*64*65);

  int tid = threadIdx.x;
  int tx = tid & 15, ty = tid >> 4;
  int qt = gridDim.x - 1 - blockIdx.x;   // heavy tiles first
  int bh = blockIdx.y;
  int b = bh >> 4, h = bh & 15;
  int q0 = qt * 64;

  const float* Qb = Q + (size_t)b * SEQ * EMBED + h * HDIM;
  const float* Kb = K + (size_t)b * SEQ * EMBED + h * HDIM;
  const float* Vb = V + (size_t)b * SEQ * EMBED + h * HDIM;

  {
    int r = tid >> 2;
    int c = (tid & 3) * 16;
    const float* src = Qb + (size_t)(q0 + r) * EMBED + c;
    #pragma unroll
    for (int u = 0; u < 4; u++) {
      float4 v4 = *(const float4*)(src + u*4);
      Qs[r][c+u*4+0] = v4.x; Qs[r][c+u*4+1] = v4.y;
      Qs[r][c+u*4+2] = v4.z; Qs[r][c+u*4+3] = v4.w;
    }
  }

  float m[4], l[4], acc[4][4];
  #pragma unroll
  for (int i = 0; i < 4; i++) {
    m[i] = -1e30f; l[i] = 0.f;
    #pragma unroll
    for (int j = 0; j < 4; j++) acc[i][j] = 0.f;
  }
  const float scale = 0.125f;

  for (int t = 0; t <= qt; t++) {
    int k0t = t * 64;
    __syncthreads();
    {
      int r = tid >> 2;
      int c = (tid & 3) * 16;
      const float* ks = Kb + (size_t)(k0t + r) * EMBED + c;
      const float* vs = Vb + (size_t)(k0t + r) * EMBED + c;
      #pragma unroll
      for (int u = 0; u < 4; u++) {
        float4 kv = *(const float4*)(ks + u*4);
        Ks[r][c+u*4+0] = kv.x; Ks[r][c+u*4+1] = kv.y;
        Ks[r][c+u*4+2] = kv.z; Ks[r][c+u*4+3] = kv.w;
        float4 vv = *(const float4*)(vs + u*4);
        Vs[r][c+u*4+0] = vv.x; Vs[r][c+u*4+1] = vv.y;
        Vs[r][c+u*4+2] = vv.z; Vs[r][c+u*4+3] = vv.w;
      }
    }
    __syncthreads();

    float s[4][4];
    #pragma unroll
    for (int i = 0; i < 4; i++)
      #pragma unroll
      for (int j = 0; j < 4; j++) s[i][j] = 0.f;
    #pragma unroll 8
    for (int k = 0; k < 64; k++) {
      float a[4], bb[4];
      #pragma unroll
      for (int i = 0; i < 4; i++) a[i]  = Qs[ty*4 + i][k];
      #pragma unroll
      for (int j = 0; j < 4; j++) bb[j] = Ks[tx*4 + j][k];
      #pragma unroll
      for (int i = 0; i < 4; i++)
        #pragma unroll
        for (int j = 0; j < 4; j++) s[i][j] = fmaf(a[i], bb[j], s[i][j]);
    }

    #pragma unroll
    for (int i = 0; i < 4; i++) {
      int qi = q0 + ty*4 + i;
      #pragma unroll
      for (int j = 0; j < 4; j++) {
        int kj = k0t + tx*4 + j;
        s[i][j] = (kj <= qi) ? s[i][j] * scale : -1e9f;
      }
    }

    #pragma unroll
    for (int i = 0; i < 4; i++) {
      float mloc = fmaxf(fmaxf(s[i][0], s[i][1]), fmaxf(s[i][2], s[i][3]));
      #pragma unroll
      for (int off = 1; off < 16; off <<= 1)
        mloc = fmaxf(mloc, __shfl_xor_sync(0xffffffffu, mloc, off));
      float mnew  = fmaxf(m[i], mloc);
      float alpha = __expf(m[i] - mnew);
      float lloc = 0.f;
      #pragma unroll
      for (int j = 0; j < 4; j++) {
        s[i][j] = __expf(s[i][j] - mnew);
        lloc += s[i][j];
      }
      #pragma unroll
      for (int off = 1; off < 16; off <<= 1)
        lloc += __shfl_xor_sync(0xffffffffu, lloc, off);
      l[i] = l[i] * alpha + lloc;
      m[i] = mnew;
      #pragma unroll
      for (int j = 0; j < 4; j++) acc[i][j] *= alpha;
      #pragma unroll
      for (int j = 0; j < 4; j++) Ps[ty*4 + i][tx*4 + j] = s[i][j];
    }
    __syncthreads();

    #pragma unroll 8
    for (int k = 0; k < 64; k++) {
      float p[4], vv[4];
      #pragma unroll
      for (int i = 0; i < 4; i++) p[i]  = Ps[ty*4 + i][k];
      #pragma unroll
      for (int j = 0; j < 4; j++) vv[j] = Vs[k][tx + 16*j];
      #pragma unroll
      for (int i = 0; i < 4; i++)
        #pragma unroll
        for (int j = 0; j < 4; j++) acc[i][j] = fmaf(p[i], vv[j], acc[i][j]);
    }
  }

  float* Ob = O + (size_t)b * SEQ * EMBED + h * HDIM;
  #pragma unroll
  for (int i = 0; i < 4; i++) {
    int r = q0 + ty*4 + i;
    float inv = 1.f / l[i];
    #pragma unroll
    for (int j = 0; j < 4; j++)
      Ob[(size_t)r * EMBED + tx + 16*j] = acc[i][j] * inv;
  }
}

// ---------------------------------------------------------------------------
extern "C" void kernel_launch(void* const* d_in, const int* in_sizes, int n_in,
                              void* d_out, int out_size) {
  (void)in_sizes; (void)n_in; (void)out_size;
  const float* q  = (const float*)d_in[0];
  const float* k  = (const float*)d_in[1];
  const float* v  = (const float*)d_in[2];
  // d_in[3] = mask (tril) — causal structure known, unused
  const float* Wq = (const float*)d_in[4];
  const float* bq = (const float*)d_in[5];
  const float* Wk = (const float*)d_in[6];
  const float* bk = (const float*)d_in[7];
  const float* Wv = (const float*)d_in[8];
  const float* bv = (const float*)d_in[9];
  const float* Wo = (const float*)d_in[10];
  const float* bo = (const float*)d_in[11];
  float* out = (float*)d_out;

  float *Qh, *Kh, *Vh, *Y, *Wt;
  cudaGetSymbolAddress((void**)&Qh, g_Qh);
  cudaGetSymbolAddress((void**)&Kh, g_Kh);
  cudaGetSymbolAddress((void**)&Vh, g_Vh);
  cudaGetSymbolAddress((void**)&Y,  g_Y);
  cudaGetSymbolAddress((void**)&Wt, g_Wt);

  transpose_w<<<dim3(32, 32, 4), dim3(32, 8)>>>(Wq, Wk, Wv, Wo, Wt);

  GemmArgs aq{q, Wt + 0*(size_t)EMBED*EMBED, bq, Qh};
  GemmArgs ak{k, Wt + 1*(size_t)EMBED*EMBED, bk, Kh};
  GemmArgs av{v, Wt + 2*(size_t)EMBED*EMBED, bv, Vh};
  gemm_mma<<<dim3(EMBED/128, MROWS/128, 3), 256>>>(aq, ak, av);

  const int attn_smem = 4 * 64 * 65 * sizeof(float);
  cudaFuncSetAttribute(attn_kernel,
                       cudaFuncAttributeMaxDynamicSharedMemorySize, attn_smem);
  attn_kernel<<<dim3(SEQ/64, BATCH*NHEAD), 256, attn_smem>>>(Qh, Kh, Vh, Y);

  GemmArgs ao{Y, Wt + 3*(size_t)EMBED*EMBED, bo, out};
  gemm_mma<<<dim3(EMBED/128, MROWS/128, 1), 256>>>(ao, ao, ao);
}

// round 8
// speedup vs baseline: 2.4953x; 1.7372x over previous
#include <cuda_runtime.h>
#include <cstdint>
#include <math.h>

#define EMBED 1024
#define NHEAD 16
#define HDIM  64
#define BATCH 2
#define SEQ   2048
#define MROWS (BATCH*SEQ)   // 4096

// Scratch (allocation-free rule: __device__ globals)
__device__ float g_Qh[MROWS*EMBED];
__device__ float g_Kh[MROWS*EMBED];
__device__ float g_Vh[MROWS*EMBED];
__device__ float g_Y [MROWS*EMBED];
__device__ float g_Wt[4*EMBED*EMBED];   // N-major weights, tf32-rounded bits

__device__ __forceinline__ uint32_t f2tf32(float x) {
  uint32_t r;
  asm("cvt.rna.tf32.f32 %0, %1;" : "=r"(r) : "f"(x));
  return r;
}

__device__ __forceinline__ void mma_tf32(float c[4], const uint32_t a[4],
                                         const uint32_t b[2]) {
  asm volatile(
      "mma.sync.aligned.m16n8k8.row.col.f32.tf32.tf32.f32 "
      "{%0,%1,%2,%3},{%4,%5,%6,%7},{%8,%9},{%0,%1,%2,%3};"
      : "+f"(c[0]), "+f"(c[1]), "+f"(c[2]), "+f"(c[3])
      : "r"(a[0]), "r"(a[1]), "r"(a[2]), "r"(a[3]), "r"(b[0]), "r"(b[1]));
}

// ---------------------------------------------------------------------------
// Weight transpose: Wt[n][k] = rna_tf32(W[k][n])  (N-major, pre-rounded)
// ---------------------------------------------------------------------------
__global__ __launch_bounds__(256) void transpose_w(
    const float* __restrict__ W0, const float* __restrict__ W1,
    const float* __restrict__ W2, const float* __restrict__ W3,
    float* __restrict__ Out) {
  const float* W = (blockIdx.z == 0) ? W0 : (blockIdx.z == 1) ? W1
                 : (blockIdx.z == 2) ? W2 : W3;
  float* O = Out + (size_t)blockIdx.z * EMBED * EMBED;
  __shared__ float t[32][33];
  int tx = threadIdx.x, ty = threadIdx.y;          // 32 x 8
  int x0 = blockIdx.x * 32, y0 = blockIdx.y * 32;  // x=n, y=k
  #pragma unroll
  for (int i = 0; i < 4; i++)
    t[ty + 8*i][tx] = W[(size_t)(y0 + ty + 8*i) * EMBED + x0 + tx];
  __syncthreads();
  #pragma unroll
  for (int i = 0; i < 4; i++) {
    uint32_t r = f2tf32(t[tx][ty + 8*i]);
    *(uint32_t*)&O[(size_t)(x0 + ty + 8*i) * EMBED + y0 + tx] = r;
  }
}

// ---------------------------------------------------------------------------
// tf32 mma.sync GEMM: C[128x128] = relu(A[M,K] @ Bt[N,K]^T + bias)
// ---------------------------------------------------------------------------
struct GemmArgs {
  const float* A; const float* B; const float* bias; float* C;
};

#define BK  32
#define LDS_W (BK + 4)

__global__ __launch_bounds__(256) void gemm_mma(GemmArgs g0, GemmArgs g1, GemmArgs g2) {
  GemmArgs g = (blockIdx.z == 0) ? g0 : (blockIdx.z == 1) ? g1 : g2;
  __shared__ float As[128][LDS_W];
  __shared__ float Bs[128][LDS_W];

  int tid = threadIdx.x;
  int wid = tid >> 5, lid = tid & 31;
  int gid = lid >> 2, tig = lid & 3;
  int wm = wid >> 1, wn = wid & 1;
  int m0 = blockIdx.y * 128, n0 = blockIdx.x * 128;

  const float* Arow = g.A + (size_t)m0 * EMBED;
  const float* Brow = g.B + (size_t)n0 * EMBED;

  float acc[2][8][4];
  #pragma unroll
  for (int mt = 0; mt < 2; mt++)
    #pragma unroll
    for (int nt = 0; nt < 8; nt++)
      #pragma unroll
      for (int c = 0; c < 4; c++) acc[mt][nt][c] = 0.f;

  for (int kt = 0; kt < EMBED / BK; kt++) {
    int k0 = kt * BK;
    #pragma unroll
    for (int i = 0; i < 4; i++) {
      int idx = tid + i * 256;
      int row = idx >> 3, c4 = idx & 7;
      float4 av = *(const float4*)(Arow + (size_t)row * EMBED + k0 + c4 * 4);
      float4 at;
      at.x = __uint_as_float(f2tf32(av.x));
      at.y = __uint_as_float(f2tf32(av.y));
      at.z = __uint_as_float(f2tf32(av.z));
      at.w = __uint_as_float(f2tf32(av.w));
      *(float4*)&As[row][c4 * 4] = at;
      *(float4*)&Bs[row][c4 * 4] =
          *(const float4*)(Brow + (size_t)row * EMBED + k0 + c4 * 4);
    }
    __syncthreads();

    #pragma unroll
    for (int ks = 0; ks < BK / 8; ks++) {
      int kb = ks * 8;
      uint32_t a[2][4], b[8][2];
      #pragma unroll
      for (int mt = 0; mt < 2; mt++) {
        int r0 = wm * 32 + mt * 16 + gid;
        a[mt][0] = __float_as_uint(As[r0    ][kb + tig]);
        a[mt][1] = __float_as_uint(As[r0 + 8][kb + tig]);
        a[mt][2] = __float_as_uint(As[r0    ][kb + tig + 4]);
        a[mt][3] = __float_as_uint(As[r0 + 8][kb + tig + 4]);
      }
      #pragma unroll
      for (int nt = 0; nt < 8; nt++) {
        int c0 = wn * 64 + nt * 8 + gid;
        b[nt][0] = __float_as_uint(Bs[c0][kb + tig]);
        b[nt][1] = __float_as_uint(Bs[c0][kb + tig + 4]);
      }
      #pragma unroll
      for (int mt = 0; mt < 2; mt++)
        #pragma unroll
        for (int nt = 0; nt < 8; nt++)
          mma_tf32(acc[mt][nt], a[mt], b[nt]);
    }
    __syncthreads();
  }

  #pragma unroll
  for (int mt = 0; mt < 2; mt++) {
    int row = m0 + wm * 32 + mt * 16 + gid;
    #pragma unroll
    for (int nt = 0; nt < 8; nt++) {
      int col = n0 + wn * 64 + nt * 8 + tig * 2;
      float b0 = g.bias[col], b1 = g.bias[col + 1];
      float2 o0, o1;
      o0.x = fmaxf(acc[mt][nt][0] + b0, 0.f);
      o0.y = fmaxf(acc[mt][nt][1] + b1, 0.f);
      o1.x = fmaxf(acc[mt][nt][2] + b0, 0.f);
      o1.y = fmaxf(acc[mt][nt][3] + b1, 0.f);
      *(float2*)&g.C[(size_t)row * EMBED + col] = o0;
      *(float2*)&g.C[(size_t)(row + 8) * EMBED + col] = o1;
    }
  }
}

// ---------------------------------------------------------------------------
// Flash attention on tf32 mma.sync. CTA = (b,h) x 128-query tile; KV tiles
// of 64 keys. Warp grid 4m x 2n. Q fragments live in registers (loaded once);
// the Q staging buffer is reused as the P buffer. Smem ~70 KB.
// ---------------------------------------------------------------------------
#define AW 68    // padded row width for 64-wide tiles

__global__ __launch_bounds__(256, 1) void attn_mma(
    const float* __restrict__ Q, const float* __restrict__ K,
    const float* __restrict__ V, float* __restrict__ O) {
  extern __shared__ float sm[];
  float* Ps  = sm;             // [128][AW]  (also Q staging in prologue)
  float* Ks  = sm + 128 * AW;  // [64][AW]
  float* Vs  = sm + 192 * AW;  // [64][AW]  (transposed: [dim][key])
  float* redM = sm + 256 * AW;         // [128][2]
  float* redS = sm + 256 * AW + 256;   // [128][2]

  int tid = threadIdx.x;
  int wid = tid >> 5, lid = tid & 31;
  int gid = lid >> 2, tig = lid & 3;
  int wm = wid >> 1, wn = wid & 1;

  int qt = gridDim.x - 1 - blockIdx.x;   // heavy tiles first
  int bh = blockIdx.y;
  int b = bh >> 4, h = bh & 15;
  int q0 = qt * 128;

  const float* Qb = Q + (size_t)b * SEQ * EMBED + h * HDIM;
  const float* Kb = K + (size_t)b * SEQ * EMBED + h * HDIM;
  const float* Vb = V + (size_t)b * SEQ * EMBED + h * HDIM;

  // Stage Q tile 128x64 (tf32) into the Ps region.
  #pragma unroll
  for (int i = 0; i < 8; i++) {
    int idx = tid + i * 256;           // 2048 float4
    int row = idx >> 4, c4 = idx & 15;
    float4 v4 = *(const float4*)(Qb + (size_t)(q0 + row) * EMBED + c4 * 4);
    float4 t;
    t.x = __uint_as_float(f2tf32(v4.x));
    t.y = __uint_as_float(f2tf32(v4.y));
    t.z = __uint_as_float(f2tf32(v4.z));
    t.w = __uint_as_float(f2tf32(v4.w));
    *(float4*)&Ps[row * AW + c4 * 4] = t;
  }
  __syncthreads();

  // Pull Q fragments into registers (loop-invariant).
  uint32_t qf[8][2][4];
  #pragma unroll
  for (int ks = 0; ks < 8; ks++) {
    int kb = ks * 8;
    #pragma unroll
    for (int mt = 0; mt < 2; mt++) {
      int r0 = wm * 32 + mt * 16 + gid;
      qf[ks][mt][0] = __float_as_uint(Ps[r0 * AW + kb + tig]);
      qf[ks][mt][1] = __float_as_uint(Ps[(r0 + 8) * AW + kb + tig]);
      qf[ks][mt][2] = __float_as_uint(Ps[r0 * AW + kb + tig + 4]);
      qf[ks][mt][3] = __float_as_uint(Ps[(r0 + 8) * AW + kb + tig + 4]);
    }
  }
  // NOTE: first Ps overwrite happens after the K/V-load __syncthreads()
  // below, which orders it after all qf reads above.

  int base = wm * 32 + gid;
  int rows[4] = {base, base + 8, base + 16, base + 24};
  float mrun[4] = {-1e9f, -1e9f, -1e9f, -1e9f};
  float lrun[4] = {0.f, 0.f, 0.f, 0.f};
  float oacc[2][4][4];
  #pragma unroll
  for (int mt = 0; mt < 2; mt++)
    #pragma unroll
    for (int nt = 0; nt < 4; nt++)
      #pragma unroll
      for (int c = 0; c < 4; c++) oacc[mt][nt][c] = 0.f;

  const float scale = 0.125f;
  int ntiles = 2 * qt + 2;

  for (int t = 0; t < ntiles; t++) {
    int k0 = t * 64;
    if (t) __syncthreads();   // Ks/Vs/Ps safe to overwrite

    // Load K (row-major, tf32) and V (transposed to [dim][key], tf32).
    #pragma unroll
    for (int i = 0; i < 4; i++) {
      int idx = tid + i * 256;           // 1024 float4
      int row = idx >> 4, c4 = idx & 15; // row = key index
      float4 kv = *(const float4*)(Kb + (size_t)(k0 + row) * EMBED + c4 * 4);
      float4 kt;
      kt.x = __uint_as_float(f2tf32(kv.x));
      kt.y = __uint_as_float(f2tf32(kv.y));
      kt.z = __uint_as_float(f2tf32(kv.z));
      kt.w = __uint_as_float(f2tf32(kv.w));
      *(float4*)&Ks[row * AW + c4 * 4] = kt;
      float4 vv = *(const float4*)(Vb + (size_t)(k0 + row) * EMBED + c4 * 4);
      Vs[(c4 * 4 + 0) * AW + row] = __uint_as_float(f2tf32(vv.x));
      Vs[(c4 * 4 + 1) * AW + row] = __uint_as_float(f2tf32(vv.y));
      Vs[(c4 * 4 + 2) * AW + row] = __uint_as_float(f2tf32(vv.z));
      Vs[(c4 * 4 + 3) * AW + row] = __uint_as_float(f2tf32(vv.w));
    }
    __syncthreads();

    // S = Q K^T  (128x64)
    float s[2][4][4];
    #pragma unroll
    for (int mt = 0; mt < 2; mt++)
      #pragma unroll
      for (int nt = 0; nt < 4; nt++)
        #pragma unroll
        for (int c = 0; c < 4; c++) s[mt][nt][c] = 0.f;

    #pragma unroll
    for (int ks = 0; ks < 8; ks++) {
      int kb = ks * 8;
      uint32_t bb[4][2];
      #pragma unroll
      for (int nt = 0; nt < 4; nt++) {
        int c0 = wn * 32 + nt * 8 + gid;
        bb[nt][0] = __float_as_uint(Ks[c0 * AW + kb + tig]);
        bb[nt][1] = __float_as_uint(Ks[c0 * AW + kb + tig + 4]);
      }
      #pragma unroll
      for (int mt = 0; mt < 2; mt++)
        #pragma unroll
        for (int nt = 0; nt < 4; nt++)
          mma_tf32(s[mt][nt], qf[ks][mt], bb[nt]);
    }

    // Scale + causal mask (only the 2 diagonal tiles need masking).
    bool diag = (t >= 2 * qt);
    #pragma unroll
    for (int mt = 0; mt < 2; mt++)
      #pragma unroll
      for (int nt = 0; nt < 4; nt++) {
        int col = k0 + wn * 32 + nt * 8 + 2 * tig;
        int r0 = q0 + wm * 32 + mt * 16 + gid;
        #pragma unroll
        for (int c = 0; c < 4; c++) {
          int kj = col + (c & 1);
          int qi = r0 + (c >> 1) * 8;
          float v = s[mt][nt][c] * scale;
          s[mt][nt][c] = (diag && kj > qi) ? -1e9f : v;
        }
      }

    // Row max: in-reg over nt, shuffle over tig, smem exchange over wn.
    float rmax[4];
    #pragma unroll
    for (int v = 0; v < 4; v++) {
      int mt = v >> 1, cb = (v & 1) * 2;
      float x = fmaxf(s[mt][0][cb], s[mt][0][cb + 1]);
      #pragma unroll
      for (int nt = 1; nt < 4; nt++)
        x = fmaxf(x, fmaxf(s[mt][nt][cb], s[mt][nt][cb + 1]));
      x = fmaxf(x, __shfl_xor_sync(0xffffffffu, x, 1));
      x = fmaxf(x, __shfl_xor_sync(0xffffffffu, x, 2));
      rmax[v] = x;
    }
    if (tig == 0) {
      #pragma unroll
      for (int v = 0; v < 4; v++) redM[rows[v] * 2 + wn] = rmax[v];
    }
    __syncthreads();
    float mnew[4], alpha[4];
    #pragma unroll
    for (int v = 0; v < 4; v++) {
      float tm = fmaxf(rmax[v], redM[rows[v] * 2 + (wn ^ 1)]);
      mnew[v] = fmaxf(mrun[v], tm);
      alpha[v] = __expf(mrun[v] - mnew[v]);
      mrun[v] = mnew[v];
    }

    // P = exp(S - mnew); write tf32 P to smem; accumulate row sums.
    float lloc[4] = {0.f, 0.f, 0.f, 0.f};
    #pragma unroll
    for (int mt = 0; mt < 2; mt++) {
      int r0 = wm * 32 + mt * 16 + gid;
      #pragma unroll
      for (int nt = 0; nt < 4; nt++) {
        int col = wn * 32 + nt * 8 + 2 * tig;
        float p0 = __expf(s[mt][nt][0] - mnew[2 * mt]);
        float p1 = __expf(s[mt][nt][1] - mnew[2 * mt]);
        float p2 = __expf(s[mt][nt][2] - mnew[2 * mt + 1]);
        float p3 = __expf(s[mt][nt][3] - mnew[2 * mt + 1]);
        lloc[2 * mt]     += p0 + p1;
        lloc[2 * mt + 1] += p2 + p3;
        Ps[r0 * AW + col]           = __uint_as_float(f2tf32(p0));
        Ps[r0 * AW + col + 1]       = __uint_as_float(f2tf32(p1));
        Ps[(r0 + 8) * AW + col]     = __uint_as_float(f2tf32(p2));
        Ps[(r0 + 8) * AW + col + 1] = __uint_as_float(f2tf32(p3));
      }
    }
    #pragma unroll
    for (int v = 0; v < 4; v++) {
      lloc[v] += __shfl_xor_sync(0xffffffffu, lloc[v], 1);
      lloc[v] += __shfl_xor_sync(0xffffffffu, lloc[v], 2);
    }
    if (tig == 0) {
      #pragma unroll
      for (int v = 0; v < 4; v++) redS[rows[v] * 2 + wn] = lloc[v];
    }
    __syncthreads();   // also publishes Ps for PV
    #pragma unroll
    for (int v = 0; v < 4; v++) {
      float ls = lloc[v] + redS[rows[v] * 2 + (wn ^ 1)];
      lrun[v] = lrun[v] * alpha[v] + ls;
    }
    // Rescale O accumulators.
    #pragma unroll
    for (int mt = 0; mt < 2; mt++)
      #pragma unroll
      for (int nt = 0; nt < 4; nt++) {
        oacc[mt][nt][0] *= alpha[2 * mt];
        oacc[mt][nt][1] *= alpha[2 * mt];
        oacc[mt][nt][2] *= alpha[2 * mt + 1];
        oacc[mt][nt][3] *= alpha[2 * mt + 1];
      }

    // O += P V   (128x64 x 64keys)
    #pragma unroll
    for (int ks = 0; ks < 8; ks++) {
      int kb = ks * 8;
      uint32_t a[2][4], bb[4][2];
      #pragma unroll
      for (int mt = 0; mt < 2; mt++) {
        int r0 = wm * 32 + mt * 16 + gid;
        a[mt][0] = __float_as_uint(Ps[r0 * AW + kb + tig]);
        a[mt][1] = __float_as_uint(Ps[(r0 + 8) * AW + kb + tig]);
        a[mt][2] = __float_as_uint(Ps[r0 * AW + kb + tig + 4]);
        a[mt][3] = __float_as_uint(Ps[(r0 + 8) * AW + kb + tig + 4]);
      }
      #pragma unroll
      for (int nt = 0; nt < 4; nt++) {
        int c0 = wn * 32 + nt * 8 + gid;
        bb[nt][0] = __float_as_uint(Vs[c0 * AW + kb + tig]);
        bb[nt][1] = __float_as_uint(Vs[c0 * AW + kb + tig + 4]);
      }
      #pragma unroll
      for (int mt = 0; mt < 2; mt++)
        #pragma unroll
        for (int nt = 0; nt < 4; nt++)
          mma_tf32(oacc[mt][nt], a[mt], bb[nt]);
    }
  }

  // Epilogue: O / l, store.
  float* Ob = O + (size_t)b * SEQ * EMBED + h * HDIM;
  #pragma unroll
  for (int mt = 0; mt < 2; mt++) {
    int r0 = q0 + wm * 32 + mt * 16 + gid;
    float inv0 = 1.f / lrun[2 * mt];
    float inv1 = 1.f / lrun[2 * mt + 1];
    #pragma unroll
    for (int nt = 0; nt < 4; nt++) {
      int col = wn * 32 + nt * 8 + 2 * tig;
      float2 o0, o1;
      o0.x = oacc[mt][nt][0] * inv0;
      o0.y = oacc[mt][nt][1] * inv0;
      o1.x = oacc[mt][nt][2] * inv1;
      o1.y = oacc[mt][nt][3] * inv1;
      *(float2*)&Ob[(size_t)r0 * EMBED + col] = o0;
      *(float2*)&Ob[(size_t)(r0 + 8) * EMBED + col] = o1;
    }
  }
}

// ---------------------------------------------------------------------------
extern "C" void kernel_launch(void* const* d_in, const int* in_sizes, int n_in,
                              void* d_out, int out_size) {
  (void)in_sizes; (void)n_in; (void)out_size;
  const float* q  = (const float*)d_in[0];
  const float* k  = (const float*)d_in[1];
  const float* v  = (const float*)d_in[2];
  // d_in[3] = mask (tril) — causal structure known, unused
  const float* Wq = (const float*)d_in[4];
  const float* bq = (const float*)d_in[5];
  const float* Wk = (const float*)d_in[6];
  const float* bk = (const float*)d_in[7];
  const float* Wv = (const float*)d_in[8];
  const float* bv = (const float*)d_in[9];
  const float* Wo = (const float*)d_in[10];
  const float* bo = (const float*)d_in[11];
  float* out = (float*)d_out;

  float *Qh, *Kh, *Vh, *Y, *Wt;
  cudaGetSymbolAddress((void**)&Qh, g_Qh);
  cudaGetSymbolAddress((void**)&Kh, g_Kh);
  cudaGetSymbolAddress((void**)&Vh, g_Vh);
  cudaGetSymbolAddress((void**)&Y,  g_Y);
  cudaGetSymbolAddress((void**)&Wt, g_Wt);

  transpose_w<<<dim3(32, 32, 4), dim3(32, 8)>>>(Wq, Wk, Wv, Wo, Wt);

  GemmArgs aq{q, Wt + 0*(size_t)EMBED*EMBED, bq, Qh};
  GemmArgs ak{k, Wt + 1*(size_t)EMBED*EMBED, bk, Kh};
  GemmArgs av{v, Wt + 2*(size_t)EMBED*EMBED, bv, Vh};
  gemm_mma<<<dim3(EMBED/128, MROWS/128, 3), 256>>>(aq, ak, av);

  const int attn_smem = (256 * AW + 512) * sizeof(float);  // 71680 B
  cudaFuncSetAttribute(attn_mma,
                       cudaFuncAttributeMaxDynamicSharedMemorySize, attn_smem);
  attn_mma<<<dim3(SEQ/128, BATCH*NHEAD), 256, attn_smem>>>(Qh, Kh, Vh, Y);

  GemmArgs ao{Y, Wt + 3*(size_t)EMBED*EMBED, bo, out};
  gemm_mma<<<dim3(EMBED/128, MROWS/128, 1), 256>>>(ao, ao, ao);
}

// round 9
// speedup vs baseline: 2.5267x; 1.0126x over previous
#include <cuda_runtime.h>
#include <cstdint>
#include <math.h>

#define EMBED 1024
#define NHEAD 16
#define HDIM  64
#define BATCH 2
#define SEQ   2048
#define MROWS (BATCH*SEQ)   // 4096

// Scratch (allocation-free rule: __device__ globals)
__device__ float g_Qh[MROWS*EMBED];
__device__ float g_Kh[MROWS*EMBED];
__device__ float g_Vh[MROWS*EMBED];
__device__ float g_Y [MROWS*EMBED];
__device__ float g_Wt[4*EMBED*EMBED];   // N-major weights, tf32-rounded bits

__device__ __forceinline__ uint32_t f2tf32(float x) {
  uint32_t r;
  asm("cvt.rna.tf32.f32 %0, %1;" : "=r"(r) : "f"(x));
  return r;
}

__device__ __forceinline__ void mma_tf32(float c[4], const uint32_t a[4],
                                         const uint32_t b[2]) {
  asm volatile(
      "mma.sync.aligned.m16n8k8.row.col.f32.tf32.tf32.f32 "
      "{%0,%1,%2,%3},{%4,%5,%6,%7},{%8,%9},{%0,%1,%2,%3};"
      : "+f"(c[0]), "+f"(c[1]), "+f"(c[2]), "+f"(c[3])
      : "r"(a[0]), "r"(a[1]), "r"(a[2]), "r"(a[3]), "r"(b[0]), "r"(b[1]));
}

// ---------------------------------------------------------------------------
// Weight transpose: Wt[n][k] = rna_tf32(W[k][n])  (N-major, pre-rounded)
// ---------------------------------------------------------------------------
__global__ __launch_bounds__(256) void transpose_w(
    const float* __restrict__ W0, const float* __restrict__ W1,
    const float* __restrict__ W2, const float* __restrict__ W3,
    float* __restrict__ Out) {
  const float* W = (blockIdx.z == 0) ? W0 : (blockIdx.z == 1) ? W1
                 : (blockIdx.z == 2) ? W2 : W3;
  float* O = Out + (size_t)blockIdx.z * EMBED * EMBED;
  __shared__ float t[32][33];
  int tx = threadIdx.x, ty = threadIdx.y;          // 32 x 8
  int x0 = blockIdx.x * 32, y0 = blockIdx.y * 32;  // x=n, y=k
  #pragma unroll
  for (int i = 0; i < 4; i++)
    t[ty + 8*i][tx] = W[(size_t)(y0 + ty + 8*i) * EMBED + x0 + tx];
  __syncthreads();
  #pragma unroll
  for (int i = 0; i < 4; i++) {
    uint32_t r = f2tf32(t[tx][ty + 8*i]);
    *(uint32_t*)&O[(size_t)(x0 + ty + 8*i) * EMBED + y0 + tx] = r;
  }
}

// ---------------------------------------------------------------------------
// tf32 mma.sync GEMM: C[128x128] = relu(A[M,K] @ Bt[N,K]^T + bias)
// ---------------------------------------------------------------------------
struct GemmArgs {
  const float* A; const float* B; const float* bias; float* C;
};

#define BK  32
#define LDS_W (BK + 4)

__global__ __launch_bounds__(256) void gemm_mma(GemmArgs g0, GemmArgs g1, GemmArgs g2) {
  GemmArgs g = (blockIdx.z == 0) ? g0 : (blockIdx.z == 1) ? g1 : g2;
  __shared__ float As[128][LDS_W];
  __shared__ float Bs[128][LDS_W];

  int tid = threadIdx.x;
  int wid = tid >> 5, lid = tid & 31;
  int gid = lid >> 2, tig = lid & 3;
  int wm = wid >> 1, wn = wid & 1;
  int m0 = blockIdx.y * 128, n0 = blockIdx.x * 128;

  const float* Arow = g.A + (size_t)m0 * EMBED;
  const float* Brow = g.B + (size_t)n0 * EMBED;

  float acc[2][8][4];
  #pragma unroll
  for (int mt = 0; mt < 2; mt++)
    #pragma unroll
    for (int nt = 0; nt < 8; nt++)
      #pragma unroll
      for (int c = 0; c < 4; c++) acc[mt][nt][c] = 0.f;

  for (int kt = 0; kt < EMBED / BK; kt++) {
    int k0 = kt * BK;
    #pragma unroll
    for (int i = 0; i < 4; i++) {
      int idx = tid + i * 256;
      int row = idx >> 3, c4 = idx & 7;
      float4 av = *(const float4*)(Arow + (size_t)row * EMBED + k0 + c4 * 4);
      float4 at;
      at.x = __uint_as_float(f2tf32(av.x));
      at.y = __uint_as_float(f2tf32(av.y));
      at.z = __uint_as_float(f2tf32(av.z));
      at.w = __uint_as_float(f2tf32(av.w));
      *(float4*)&As[row][c4 * 4] = at;
      *(float4*)&Bs[row][c4 * 4] =
          *(const float4*)(Brow + (size_t)row * EMBED + k0 + c4 * 4);
    }
    __syncthreads();

    #pragma unroll
    for (int ks = 0; ks < BK / 8; ks++) {
      int kb = ks * 8;
      uint32_t a[2][4], b[8][2];
      #pragma unroll
      for (int mt = 0; mt < 2; mt++) {
        int r0 = wm * 32 + mt * 16 + gid;
        a[mt][0] = __float_as_uint(As[r0    ][kb + tig]);
        a[mt][1] = __float_as_uint(As[r0 + 8][kb + tig]);
        a[mt][2] = __float_as_uint(As[r0    ][kb + tig + 4]);
        a[mt][3] = __float_as_uint(As[r0 + 8][kb + tig + 4]);
      }
      #pragma unroll
      for (int nt = 0; nt < 8; nt++) {
        int c0 = wn * 64 + nt * 8 + gid;
        b[nt][0] = __float_as_uint(Bs[c0][kb + tig]);
        b[nt][1] = __float_as_uint(Bs[c0][kb + tig + 4]);
      }
      #pragma unroll
      for (int mt = 0; mt < 2; mt++)
        #pragma unroll
        for (int nt = 0; nt < 8; nt++)
          mma_tf32(acc[mt][nt], a[mt], b[nt]);
    }
    __syncthreads();
  }

  #pragma unroll
  for (int mt = 0; mt < 2; mt++) {
    int row = m0 + wm * 32 + mt * 16 + gid;
    #pragma unroll
    for (int nt = 0; nt < 8; nt++) {
      int col = n0 + wn * 64 + nt * 8 + tig * 2;
      float b0 = g.bias[col], b1 = g.bias[col + 1];
      float2 o0, o1;
      o0.x = fmaxf(acc[mt][nt][0] + b0, 0.f);
      o0.y = fmaxf(acc[mt][nt][1] + b1, 0.f);
      o1.x = fmaxf(acc[mt][nt][2] + b0, 0.f);
      o1.y = fmaxf(acc[mt][nt][3] + b1, 0.f);
      *(float2*)&g.C[(size_t)row * EMBED + col] = o0;
      *(float2*)&g.C[(size_t)(row + 8) * EMBED + col] = o1;
    }
  }
}

// ---------------------------------------------------------------------------
// Flash attention on tf32 mma.sync. CTA = (b,h) x 128-query tile; KV tiles
// of 64 keys. Q fragments in registers; K/V register-prefetch double
// buffering: tile t+1's global loads issue before tile t's compute,
// hiding DRAM/L2 latency. Smem 71.7 KB (single K/V buffer).
// ---------------------------------------------------------------------------
#define AW 68    // padded row width for 64-wide tiles

__global__ __launch_bounds__(256, 1) void attn_mma(
    const float* __restrict__ Q, const float* __restrict__ K,
    const float* __restrict__ V, float* __restrict__ O) {
  extern __shared__ float sm[];
  float* Ps  = sm;             // [128][AW]  (also Q staging in prologue)
  float* Ks  = sm + 128 * AW;  // [64][AW]
  float* Vs  = sm + 192 * AW;  // [64][AW]  (transposed: [dim][key])
  float* redM = sm + 256 * AW;         // [128][2]
  float* redS = sm + 256 * AW + 256;   // [128][2]

  int tid = threadIdx.x;
  int wid = tid >> 5, lid = tid & 31;
  int gid = lid >> 2, tig = lid & 3;
  int wm = wid >> 1, wn = wid & 1;

  int qt = gridDim.x - 1 - blockIdx.x;   // heavy tiles first
  int bh = blockIdx.y;
  int b = bh >> 4, h = bh & 15;
  int q0 = qt * 128;

  const float* Qb = Q + (size_t)b * SEQ * EMBED + h * HDIM;
  const float* Kb = K + (size_t)b * SEQ * EMBED + h * HDIM;
  const float* Vb = V + (size_t)b * SEQ * EMBED + h * HDIM;

  // Per-thread load coords (same for every tile).
  int ldrow = tid >> 2;            // 0..63   key index
  int ldc4  = (tid & 3) * 4;       // 0,4,8,12  float4 slot (x4 iters -> 16)

  // Stage Q tile 128x64 (tf32) into the Ps region.
  #pragma unroll
  for (int i = 0; i < 8; i++) {
    int idx = tid + i * 256;           // 2048 float4
    int row = idx >> 4, c4 = idx & 15;
    float4 v4 = *(const float4*)(Qb + (size_t)(q0 + row) * EMBED + c4 * 4);
    float4 t;
    t.x = __uint_as_float(f2tf32(v4.x));
    t.y = __uint_as_float(f2tf32(v4.y));
    t.z = __uint_as_float(f2tf32(v4.z));
    t.w = __uint_as_float(f2tf32(v4.w));
    *(float4*)&Ps[row * AW + c4 * 4] = t;
  }
  __syncthreads();

  // Pull Q fragments into registers (loop-invariant).
  uint32_t qf[8][2][4];
  #pragma unroll
  for (int ks = 0; ks < 8; ks++) {
    int kb = ks * 8;
    #pragma unroll
    for (int mt = 0; mt < 2; mt++) {
      int r0 = wm * 32 + mt * 16 + gid;
      qf[ks][mt][0] = __float_as_uint(Ps[r0 * AW + kb + tig]);
      qf[ks][mt][1] = __float_as_uint(Ps[(r0 + 8) * AW + kb + tig]);
      qf[ks][mt][2] = __float_as_uint(Ps[r0 * AW + kb + tig + 4]);
      qf[ks][mt][3] = __float_as_uint(Ps[(r0 + 8) * AW + kb + tig + 4]);
    }
  }

  int base = wm * 32 + gid;
  int rows[4] = {base, base + 8, base + 16, base + 24};
  float mrun[4] = {-1e9f, -1e9f, -1e9f, -1e9f};
  float lrun[4] = {0.f, 0.f, 0.f, 0.f};
  float oacc[2][4][4];
  #pragma unroll
  for (int mt = 0; mt < 2; mt++)
    #pragma unroll
    for (int nt = 0; nt < 4; nt++)
      #pragma unroll
      for (int c = 0; c < 4; c++) oacc[mt][nt][c] = 0.f;

  const float scale = 0.125f;
  int ntiles = 2 * qt + 2;

  // Prefetch tile 0 K/V into registers.
  float4 kreg[4], vreg[4];
  #pragma unroll
  for (int i = 0; i < 4; i++) {
    int row = (tid + i * 256) >> 4;
    int c4  = (tid + i * 256) & 15;
    kreg[i] = *(const float4*)(Kb + (size_t)row * EMBED + c4 * 4);
    vreg[i] = *(const float4*)(Vb + (size_t)row * EMBED + c4 * 4);
  }

  for (int t = 0; t < ntiles; t++) {
    __syncthreads();   // prior tile's smem readers (incl. qf reads at t=0) done

    // Store staged tile t K/V registers into smem (tf32 cvt here).
    #pragma unroll
    for (int i = 0; i < 4; i++) {
      int idx = tid + i * 256;
      int row = idx >> 4, c4 = idx & 15;
      float4 kt;
      kt.x = __uint_as_float(f2tf32(kreg[i].x));
      kt.y = __uint_as_float(f2tf32(kreg[i].y));
      kt.z = __uint_as_float(f2tf32(kreg[i].z));
      kt.w = __uint_as_float(f2tf32(kreg[i].w));
      *(float4*)&Ks[row * AW + c4 * 4] = kt;
      Vs[(c4 * 4 + 0) * AW + row] = __uint_as_float(f2tf32(vreg[i].x));
      Vs[(c4 * 4 + 1) * AW + row] = __uint_as_float(f2tf32(vreg[i].y));
      Vs[(c4 * 4 + 2) * AW + row] = __uint_as_float(f2tf32(vreg[i].z));
      Vs[(c4 * 4 + 3) * AW + row] = __uint_as_float(f2tf32(vreg[i].w));
    }
    __syncthreads();   // Ks/Vs published

    // Issue tile t+1 global loads NOW; latency hides behind this tile's math.
    if (t + 1 < ntiles) {
      int k0n = (t + 1) * 64;
      #pragma unroll
      for (int i = 0; i < 4; i++) {
        int row = (tid + i * 256) >> 4;
        int c4  = (tid + i * 256) & 15;
        kreg[i] = *(const float4*)(Kb + (size_t)(k0n + row) * EMBED + c4 * 4);
        vreg[i] = *(const float4*)(Vb + (size_t)(k0n + row) * EMBED + c4 * 4);
      }
    }

    int k0 = t * 64;

    // S = Q K^T  (128x64)
    float s[2][4][4];
    #pragma unroll
    for (int mt = 0; mt < 2; mt++)
      #pragma unroll
      for (int nt = 0; nt < 4; nt++)
        #pragma unroll
        for (int c = 0; c < 4; c++) s[mt][nt][c] = 0.f;

    #pragma unroll
    for (int ks = 0; ks < 8; ks++) {
      int kb = ks * 8;
      uint32_t bb[4][2];
      #pragma unroll
      for (int nt = 0; nt < 4; nt++) {
        int c0 = wn * 32 + nt * 8 + gid;
        bb[nt][0] = __float_as_uint(Ks[c0 * AW + kb + tig]);
        bb[nt][1] = __float_as_uint(Ks[c0 * AW + kb + tig + 4]);
      }
      #pragma unroll
      for (int mt = 0; mt < 2; mt++)
        #pragma unroll
        for (int nt = 0; nt < 4; nt++)
          mma_tf32(s[mt][nt], qf[ks][mt], bb[nt]);
    }

    // Scale + causal mask (only the 2 diagonal tiles need masking).
    bool diag = (t >= 2 * qt);
    #pragma unroll
    for (int mt = 0; mt < 2; mt++)
      #pragma unroll
      for (int nt = 0; nt < 4; nt++) {
        int col = k0 + wn * 32 + nt * 8 + 2 * tig;
        int r0 = q0 + wm * 32 + mt * 16 + gid;
        #pragma unroll
        for (int c = 0; c < 4; c++) {
          int kj = col + (c & 1);
          int qi = r0 + (c >> 1) * 8;
          float v = s[mt][nt][c] * scale;
          s[mt][nt][c] = (diag && kj > qi) ? -1e9f : v;
        }
      }

    // Row max: in-reg over nt, shuffle over tig, smem exchange over wn.
    float rmax[4];
    #pragma unroll
    for (int v = 0; v < 4; v++) {
      int mt = v >> 1, cb = (v & 1) * 2;
      float x = fmaxf(s[mt][0][cb], s[mt][0][cb + 1]);
      #pragma unroll
      for (int nt = 1; nt < 4; nt++)
        x = fmaxf(x, fmaxf(s[mt][nt][cb], s[mt][nt][cb + 1]));
      x = fmaxf(x, __shfl_xor_sync(0xffffffffu, x, 1));
      x = fmaxf(x, __shfl_xor_sync(0xffffffffu, x, 2));
      rmax[v] = x;
    }
    if (tig == 0) {
      #pragma unroll
      for (int v = 0; v < 4; v++) redM[rows[v] * 2 + wn] = rmax[v];
    }
    __syncthreads();
    float mnew[4], alpha[4];
    #pragma unroll
    for (int v = 0; v < 4; v++) {
      float tm = fmaxf(rmax[v], redM[rows[v] * 2 + (wn ^ 1)]);
      mnew[v] = fmaxf(mrun[v], tm);
      alpha[v] = __expf(mrun[v] - mnew[v]);
      mrun[v] = mnew[v];
    }

    // P = exp(S - mnew); write tf32 P to smem; accumulate row sums.
    float lloc[4] = {0.f, 0.f, 0.f, 0.f};
    #pragma unroll
    for (int mt = 0; mt < 2; mt++) {
      int r0 = wm * 32 + mt * 16 + gid;
      #pragma unroll
      for (int nt = 0; nt < 4; nt++) {
        int col = wn * 32 + nt * 8 + 2 * tig;
        float p0 = __expf(s[mt][nt][0] - mnew[2 * mt]);
        float p1 = __expf(s[mt][nt][1] - mnew[2 * mt]);
        float p2 = __expf(s[mt][nt][2] - mnew[2 * mt + 1]);
        float p3 = __expf(s[mt][nt][3] - mnew[2 * mt + 1]);
        lloc[2 * mt]     += p0 + p1;
        lloc[2 * mt + 1] += p2 + p3;
        Ps[r0 * AW + col]           = __uint_as_float(f2tf32(p0));
        Ps[r0 * AW + col + 1]       = __uint_as_float(f2tf32(p1));
        Ps[(r0 + 8) * AW + col]     = __uint_as_float(f2tf32(p2));
        Ps[(r0 + 8) * AW + col + 1] = __uint_as_float(f2tf32(p3));
      }
    }
    #pragma unroll
    for (int v = 0; v < 4; v++) {
      lloc[v] += __shfl_xor_sync(0xffffffffu, lloc[v], 1);
      lloc[v] += __shfl_xor_sync(0xffffffffu, lloc[v], 2);
    }
    if (tig == 0) {
      #pragma unroll
      for (int v = 0; v < 4; v++) redS[rows[v] * 2 + wn] = lloc[v];
    }
    __syncthreads();   // also publishes Ps for PV
    #pragma unroll
    for (int v = 0; v < 4; v++) {
      float ls = lloc[v] + redS[rows[v] * 2 + (wn ^ 1)];
      lrun[v] = lrun[v] * alpha[v] + ls;
    }
    // Rescale O accumulators.
    #pragma unroll
    for (int mt = 0; mt < 2; mt++)
      #pragma unroll
      for (int nt = 0; nt < 4; nt++) {
        oacc[mt][nt][0] *= alpha[2 * mt];
        oacc[mt][nt][1] *= alpha[2 * mt];
        oacc[mt][nt][2] *= alpha[2 * mt + 1];
        oacc[mt][nt][3] *= alpha[2 * mt + 1];
      }

    // O += P V   (128x64 x 64keys)
    #pragma unroll
    for (int ks = 0; ks < 8; ks++) {
      int kb = ks * 8;
      uint32_t a[2][4], bb[4][2];
      #pragma unroll
      for (int mt = 0; mt < 2; mt++) {
        int r0 = wm * 32 + mt * 16 + gid;
        a[mt][0] = __float_as_uint(Ps[r0 * AW + kb + tig]);
        a[mt][1] = __float_as_uint(Ps[(r0 + 8) * AW + kb + tig]);
        a[mt][2] = __float_as_uint(Ps[r0 * AW + kb + tig + 4]);
        a[mt][3] = __float_as_uint(Ps[(r0 + 8) * AW + kb + tig + 4]);
      }
      #pragma unroll
      for (int nt = 0; nt < 4; nt++) {
        int c0 = wn * 32 + nt * 8 + gid;
        bb[nt][0] = __float_as_uint(Vs[c0 * AW + kb + tig]);
        bb[nt][1] = __float_as_uint(Vs[c0 * AW + kb + tig + 4]);
      }
      #pragma unroll
      for (int mt = 0; mt < 2; mt++)
        #pragma unroll
        for (int nt = 0; nt < 4; nt++)
          mma_tf32(oacc[mt][nt], a[mt], bb[nt]);
    }
  }

  // Epilogue: O / l, store.
  float* Ob = O + (size_t)b * SEQ * EMBED + h * HDIM;
  #pragma unroll
  for (int mt = 0; mt < 2; mt++) {
    int r0 = q0 + wm * 32 + mt * 16 + gid;
    float inv0 = 1.f / lrun[2 * mt];
    float inv1 = 1.f / lrun[2 * mt + 1];
    #pragma unroll
    for (int nt = 0; nt < 4; nt++) {
      int col = wn * 32 + nt * 8 + 2 * tig;
      float2 o0, o1;
      o0.x = oacc[mt][nt][0] * inv0;
      o0.y = oacc[mt][nt][1] * inv0;
      o1.x = oacc[mt][nt][2] * inv1;
      o1.y = oacc[mt][nt][3] * inv1;
      *(float2*)&Ob[(size_t)r0 * EMBED + col] = o0;
      *(float2*)&Ob[(size_t)(r0 + 8) * EMBED + col] = o1;
    }
  }
}

// ---------------------------------------------------------------------------
extern "C" void kernel_launch(void* const* d_in, const int* in_sizes, int n_in,
                              void* d_out, int out_size) {
  (void)in_sizes; (void)n_in; (void)out_size;
  const float* q  = (const float*)d_in[0];
  const float* k  = (const float*)d_in[1];
  const float* v  = (const float*)d_in[2];
  // d_in[3] = mask (tril) — causal structure known, unused
  const float* Wq = (const float*)d_in[4];
  const float* bq = (const float*)d_in[5];
  const float* Wk = (const float*)d_in[6];
  const float* bk = (const float*)d_in[7];
  const float* Wv = (const float*)d_in[8];
  const float* bv = (const float*)d_in[9];
  const float* Wo = (const float*)d_in[10];
  const float* bo = (const float*)d_in[11];
  float* out = (float*)d_out;

  float *Qh, *Kh, *Vh, *Y, *Wt;
  cudaGetSymbolAddress((void**)&Qh, g_Qh);
  cudaGetSymbolAddress((void**)&Kh, g_Kh);
  cudaGetSymbolAddress((void**)&Vh, g_Vh);
  cudaGetSymbolAddress((void**)&Y,  g_Y);
  cudaGetSymbolAddress((void**)&Wt, g_Wt);

  transpose_w<<<dim3(32, 32, 4), dim3(32, 8)>>>(Wq, Wk, Wv, Wo, Wt);

  GemmArgs aq{q, Wt + 0*(size_t)EMBED*EMBED, bq, Qh};
  GemmArgs ak{k, Wt + 1*(size_t)EMBED*EMBED, bk, Kh};
  GemmArgs av{v, Wt + 2*(size_t)EMBED*EMBED, bv, Vh};
  gemm_mma<<<dim3(EMBED/128, MROWS/128, 3), 256>>>(aq, ak, av);

  const int attn_smem = (256 * AW + 512) * sizeof(float);  // 71680 B
  cudaFuncSetAttribute(attn_mma,
                       cudaFuncAttributeMaxDynamicSharedMemorySize, attn_smem);
  attn_mma<<<dim3(SEQ/128, BATCH*NHEAD), 256, attn_smem>>>(Qh, Kh, Vh, Y);

  GemmArgs ao{Y, Wt + 3*(size_t)EMBED*EMBED, bo, out};
  gemm_mma<<<dim3(EMBED/128, MROWS/128, 1), 256>>>(ao, ao, ao);
}

// round 10
// speedup vs baseline: 2.5841x; 1.0227x over previous
#include <cuda_runtime.h>
#include <cstdint>
#include <math.h>

#define EMBED 1024
#define NHEAD 16
#define HDIM  64
#define BATCH 2
#define SEQ   2048
#define MROWS (BATCH*SEQ)   // 4096

// Scratch (allocation-free rule: __device__ globals)
__device__ float g_Qh[MROWS*EMBED];
__device__ float g_Kh[MROWS*EMBED];
__device__ float g_Vh[MROWS*EMBED];
__device__ float g_Y [MROWS*EMBED];
__device__ float g_Wt[4*EMBED*EMBED];   // N-major weights, tf32-rounded bits

__device__ __forceinline__ uint32_t f2tf32(float x) {
  uint32_t r;
  asm("cvt.rna.tf32.f32 %0, %1;" : "=r"(r) : "f"(x));
  return r;
}

__device__ __forceinline__ void mma_tf32(float c[4], const uint32_t a[4],
                                         const uint32_t b[2]) {
  asm volatile(
      "mma.sync.aligned.m16n8k8.row.col.f32.tf32.tf32.f32 "
      "{%0,%1,%2,%3},{%4,%5,%6,%7},{%8,%9},{%0,%1,%2,%3};"
      : "+f"(c[0]), "+f"(c[1]), "+f"(c[2]), "+f"(c[3])
      : "r"(a[0]), "r"(a[1]), "r"(a[2]), "r"(a[3]), "r"(b[0]), "r"(b[1]));
}

// ---------------------------------------------------------------------------
// Weight transpose: Wt[n][k] = rna_tf32(W[k][n])  (N-major, pre-rounded)
// ---------------------------------------------------------------------------
__global__ __launch_bounds__(256) void transpose_w(
    const float* __restrict__ W0, const float* __restrict__ W1,
    const float* __restrict__ W2, const float* __restrict__ W3,
    float* __restrict__ Out) {
  const float* W = (blockIdx.z == 0) ? W0 : (blockIdx.z == 1) ? W1
                 : (blockIdx.z == 2) ? W2 : W3;
  float* O = Out + (size_t)blockIdx.z * EMBED * EMBED;
  __shared__ float t[32][33];
  int tx = threadIdx.x, ty = threadIdx.y;          // 32 x 8
  int x0 = blockIdx.x * 32, y0 = blockIdx.y * 32;  // x=n, y=k
  #pragma unroll
  for (int i = 0; i < 4; i++)
    t[ty + 8*i][tx] = W[(size_t)(y0 + ty + 8*i) * EMBED + x0 + tx];
  __syncthreads();
  #pragma unroll
  for (int i = 0; i < 4; i++) {
    uint32_t r = f2tf32(t[tx][ty + 8*i]);
    *(uint32_t*)&O[(size_t)(x0 + ty + 8*i) * EMBED + y0 + tx] = r;
  }
}

// ---------------------------------------------------------------------------
// tf32 mma.sync GEMM: C[128x128] = relu(A[M,K] @ Bt[N,K]^T + bias)
// ---------------------------------------------------------------------------
struct GemmArgs {
  const float* A; const float* B; const float* bias; float* C;
};

#define BK  32
#define LDS_W (BK + 4)

__global__ __launch_bounds__(256) void gemm_mma(GemmArgs g0, GemmArgs g1, GemmArgs g2) {
  GemmArgs g = (blockIdx.z == 0) ? g0 : (blockIdx.z == 1) ? g1 : g2;
  __shared__ float As[128][LDS_W];
  __shared__ float Bs[128][LDS_W];

  int tid = threadIdx.x;
  int wid = tid >> 5, lid = tid & 31;
  int gid = lid >> 2, tig = lid & 3;
  int wm = wid >> 1, wn = wid & 1;
  int m0 = blockIdx.y * 128, n0 = blockIdx.x * 128;

  const float* Arow = g.A + (size_t)m0 * EMBED;
  const float* Brow = g.B + (size_t)n0 * EMBED;

  float acc[2][8][4];
  #pragma unroll
  for (int mt = 0; mt < 2; mt++)
    #pragma unroll
    for (int nt = 0; nt < 8; nt++)
      #pragma unroll
      for (int c = 0; c < 4; c++) acc[mt][nt][c] = 0.f;

  for (int kt = 0; kt < EMBED / BK; kt++) {
    int k0 = kt * BK;
    #pragma unroll
    for (int i = 0; i < 4; i++) {
      int idx = tid + i * 256;
      int row = idx >> 3, c4 = idx & 7;
      float4 av = *(const float4*)(Arow + (size_t)row * EMBED + k0 + c4 * 4);
      float4 at;
      at.x = __uint_as_float(f2tf32(av.x));
      at.y = __uint_as_float(f2tf32(av.y));
      at.z = __uint_as_float(f2tf32(av.z));
      at.w = __uint_as_float(f2tf32(av.w));
      *(float4*)&As[row][c4 * 4] = at;
      *(float4*)&Bs[row][c4 * 4] =
          *(const float4*)(Brow + (size_t)row * EMBED + k0 + c4 * 4);
    }
    __syncthreads();

    #pragma unroll
    for (int ks = 0; ks < BK / 8; ks++) {
      int kb = ks * 8;
      uint32_t a[2][4], b[8][2];
      #pragma unroll
      for (int mt = 0; mt < 2; mt++) {
        int r0 = wm * 32 + mt * 16 + gid;
        a[mt][0] = __float_as_uint(As[r0    ][kb + tig]);
        a[mt][1] = __float_as_uint(As[r0 + 8][kb + tig]);
        a[mt][2] = __float_as_uint(As[r0    ][kb + tig + 4]);
        a[mt][3] = __float_as_uint(As[r0 + 8][kb + tig + 4]);
      }
      #pragma unroll
      for (int nt = 0; nt < 8; nt++) {
        int c0 = wn * 64 + nt * 8 + gid;
        b[nt][0] = __float_as_uint(Bs[c0][kb + tig]);
        b[nt][1] = __float_as_uint(Bs[c0][kb + tig + 4]);
      }
      #pragma unroll
      for (int mt = 0; mt < 2; mt++)
        #pragma unroll
        for (int nt = 0; nt < 8; nt++)
          mma_tf32(acc[mt][nt], a[mt], b[nt]);
    }
    __syncthreads();
  }

  #pragma unroll
  for (int mt = 0; mt < 2; mt++) {
    int row = m0 + wm * 32 + mt * 16 + gid;
    #pragma unroll
    for (int nt = 0; nt < 8; nt++) {
      int col = n0 + wn * 64 + nt * 8 + tig * 2;
      float b0 = g.bias[col], b1 = g.bias[col + 1];
      float2 o0, o1;
      o0.x = fmaxf(acc[mt][nt][0] + b0, 0.f);
      o0.y = fmaxf(acc[mt][nt][1] + b1, 0.f);
      o1.x = fmaxf(acc[mt][nt][2] + b0, 0.f);
      o1.y = fmaxf(acc[mt][nt][3] + b1, 0.f);
      *(float2*)&g.C[(size_t)row * EMBED + col] = o0;
      *(float2*)&g.C[(size_t)(row + 8) * EMBED + col] = o1;
    }
  }
}

// ---------------------------------------------------------------------------
// Flash attention on tf32 mma.sync. CTA = (b,h) x 128-query tile; KV tiles
// of 64 keys. Warp layout 8m x 1n: each warp owns 16 FULL rows of S/P/O, so
// softmax is warp-local (no cross-warp exchange, no block syncs in softmax,
// PV ordering via __syncwarp only). 2 block syncs per tile (K/V buffer).
// ---------------------------------------------------------------------------
#define AW 68    // padded row width for 64-wide tiles

__global__ __launch_bounds__(256, 1) void attn_mma(
    const float* __restrict__ Q, const float* __restrict__ K,
    const float* __restrict__ V, float* __restrict__ O) {
  extern __shared__ float sm[];
  float* Ps  = sm;             // [128][AW]  (also Q staging in prologue)
  float* Ks  = sm + 128 * AW;  // [64][AW]
  float* Vs  = sm + 192 * AW;  // [64][AW]  (transposed: [dim][key])

  int tid = threadIdx.x;
  int wid = tid >> 5, lid = tid & 31;
  int gid = lid >> 2, tig = lid & 3;

  int qt = gridDim.x - 1 - blockIdx.x;   // heavy tiles first
  int bh = blockIdx.y;
  int b = bh >> 4, h = bh & 15;
  int q0 = qt * 128;
  int wrow = wid * 16 + gid;             // this thread's row pair: wrow, wrow+8

  const float* Qb = Q + (size_t)b * SEQ * EMBED + h * HDIM;
  const float* Kb = K + (size_t)b * SEQ * EMBED + h * HDIM;
  const float* Vb = V + (size_t)b * SEQ * EMBED + h * HDIM;

  // Stage Q tile 128x64 (tf32) into the Ps region.
  #pragma unroll
  for (int i = 0; i < 8; i++) {
    int idx = tid + i * 256;           // 2048 float4
    int row = idx >> 4, c4 = idx & 15;
    float4 v4 = *(const float4*)(Qb + (size_t)(q0 + row) * EMBED + c4 * 4);
    float4 t;
    t.x = __uint_as_float(f2tf32(v4.x));
    t.y = __uint_as_float(f2tf32(v4.y));
    t.z = __uint_as_float(f2tf32(v4.z));
    t.w = __uint_as_float(f2tf32(v4.w));
    *(float4*)&Ps[row * AW + c4 * 4] = t;
  }
  __syncthreads();

  // Pull Q fragments into registers (own warp's 16 rows; loop-invariant).
  uint32_t qf[8][4];
  #pragma unroll
  for (int ks = 0; ks < 8; ks++) {
    int kb = ks * 8;
    qf[ks][0] = __float_as_uint(Ps[wrow * AW + kb + tig]);
    qf[ks][1] = __float_as_uint(Ps[(wrow + 8) * AW + kb + tig]);
    qf[ks][2] = __float_as_uint(Ps[wrow * AW + kb + tig + 4]);
    qf[ks][3] = __float_as_uint(Ps[(wrow + 8) * AW + kb + tig + 4]);
  }

  float mrun[2] = {-1e9f, -1e9f};
  float lrun[2] = {0.f, 0.f};
  float oacc[8][4];
  #pragma unroll
  for (int nt = 0; nt < 8; nt++)
    #pragma unroll
    for (int c = 0; c < 4; c++) oacc[nt][c] = 0.f;

  const float scale = 0.125f;
  int ntiles = 2 * qt + 2;

  // Prefetch tile 0 K/V into registers.
  float4 kreg[4], vreg[4];
  #pragma unroll
  for (int i = 0; i < 4; i++) {
    int row = (tid + i * 256) >> 4;
    int c4  = (tid + i * 256) & 15;
    kreg[i] = *(const float4*)(Kb + (size_t)row * EMBED + c4 * 4);
    vreg[i] = *(const float4*)(Vb + (size_t)row * EMBED + c4 * 4);
  }

  for (int t = 0; t < ntiles; t++) {
    __syncthreads();   // prior tile's Ks/Vs readers (and t=0 qf reads) done

    // Store staged tile t K/V registers into smem (tf32 cvt here).
    #pragma unroll
    for (int i = 0; i < 4; i++) {
      int idx = tid + i * 256;
      int row = idx >> 4, c4 = idx & 15;
      float4 kt;
      kt.x = __uint_as_float(f2tf32(kreg[i].x));
      kt.y = __uint_as_float(f2tf32(kreg[i].y));
      kt.z = __uint_as_float(f2tf32(kreg[i].z));
      kt.w = __uint_as_float(f2tf32(kreg[i].w));
      *(float4*)&Ks[row * AW + c4 * 4] = kt;
      Vs[(c4 * 4 + 0) * AW + row] = __uint_as_float(f2tf32(vreg[i].x));
      Vs[(c4 * 4 + 1) * AW + row] = __uint_as_float(f2tf32(vreg[i].y));
      Vs[(c4 * 4 + 2) * AW + row] = __uint_as_float(f2tf32(vreg[i].z));
      Vs[(c4 * 4 + 3) * AW + row] = __uint_as_float(f2tf32(vreg[i].w));
    }
    __syncthreads();   // Ks/Vs published

    // Issue tile t+1 global loads NOW; latency hides behind this tile's math.
    if (t + 1 < ntiles) {
      int k0n = (t + 1) * 64;
      #pragma unroll
      for (int i = 0; i < 4; i++) {
        int row = (tid + i * 256) >> 4;
        int c4  = (tid + i * 256) & 15;
        kreg[i] = *(const float4*)(Kb + (size_t)(k0n + row) * EMBED + c4 * 4);
        vreg[i] = *(const float4*)(Vb + (size_t)(k0n + row) * EMBED + c4 * 4);
      }
    }

    int k0 = t * 64;

    // S = Q K^T : this warp's 16 rows x all 64 keys (8 n-tiles).
    float s[8][4];
    #pragma unroll
    for (int nt = 0; nt < 8; nt++)
      #pragma unroll
      for (int c = 0; c < 4; c++) s[nt][c] = 0.f;

    #pragma unroll
    for (int ks = 0; ks < 8; ks++) {
      int kb = ks * 8;
      uint32_t bb[8][2];
      #pragma unroll
      for (int nt = 0; nt < 8; nt++) {
        int c0 = nt * 8 + gid;
        bb[nt][0] = __float_as_uint(Ks[c0 * AW + kb + tig]);
        bb[nt][1] = __float_as_uint(Ks[c0 * AW + kb + tig + 4]);
      }
      #pragma unroll
      for (int nt = 0; nt < 8; nt++)
        mma_tf32(s[nt], qf[ks], bb[nt]);
    }

    // Scale + causal mask (only the 2 diagonal tiles need masking).
    bool diag = (t >= 2 * qt);
    if (diag) {
      int r0 = q0 + wrow;
      #pragma unroll
      for (int nt = 0; nt < 8; nt++) {
        int col = k0 + nt * 8 + 2 * tig;
        #pragma unroll
        for (int c = 0; c < 4; c++) {
          int kj = col + (c & 1);
          int qi = r0 + (c >> 1) * 8;
          float v = s[nt][c] * scale;
          s[nt][c] = (kj > qi) ? -1e9f : v;
        }
      }
    } else {
      #pragma unroll
      for (int nt = 0; nt < 8; nt++)
        #pragma unroll
        for (int c = 0; c < 4; c++) s[nt][c] *= scale;
    }

    // Warp-local row max (2 rows per thread): in-reg over nt + 2 shuffles.
    float rmax[2];
    #pragma unroll
    for (int v = 0; v < 2; v++) {
      int cb = v * 2;
      float x = fmaxf(s[0][cb], s[0][cb + 1]);
      #pragma unroll
      for (int nt = 1; nt < 8; nt++)
        x = fmaxf(x, fmaxf(s[nt][cb], s[nt][cb + 1]));
      x = fmaxf(x, __shfl_xor_sync(0xffffffffu, x, 1));
      x = fmaxf(x, __shfl_xor_sync(0xffffffffu, x, 2));
      rmax[v] = x;
    }
    float mnew[2], alpha[2];
    #pragma unroll
    for (int v = 0; v < 2; v++) {
      mnew[v] = fmaxf(mrun[v], rmax[v]);
      alpha[v] = __expf(mrun[v] - mnew[v]);
      mrun[v] = mnew[v];
    }

    // P = exp(S - mnew); write tf32 P (own rows); accumulate row sums.
    float lloc[2] = {0.f, 0.f};
    #pragma unroll
    for (int nt = 0; nt < 8; nt++) {
      int col = nt * 8 + 2 * tig;
      float p0 = __expf(s[nt][0] - mnew[0]);
      float p1 = __expf(s[nt][1] - mnew[0]);
      float p2 = __expf(s[nt][2] - mnew[1]);
      float p3 = __expf(s[nt][3] - mnew[1]);
      lloc[0] += p0 + p1;
      lloc[1] += p2 + p3;
      Ps[wrow * AW + col]           = __uint_as_float(f2tf32(p0));
      Ps[wrow * AW + col + 1]       = __uint_as_float(f2tf32(p1));
      Ps[(wrow + 8) * AW + col]     = __uint_as_float(f2tf32(p2));
      Ps[(wrow + 8) * AW + col + 1] = __uint_as_float(f2tf32(p3));
    }
    #pragma unroll
    for (int v = 0; v < 2; v++) {
      lloc[v] += __shfl_xor_sync(0xffffffffu, lloc[v], 1);
      lloc[v] += __shfl_xor_sync(0xffffffffu, lloc[v], 2);
      lrun[v] = lrun[v] * alpha[v] + lloc[v];
    }
    // Rescale O accumulators.
    #pragma unroll
    for (int nt = 0; nt < 8; nt++) {
      oacc[nt][0] *= alpha[0];
      oacc[nt][1] *= alpha[0];
      oacc[nt][2] *= alpha[1];
      oacc[nt][3] *= alpha[1];
    }

    __syncwarp();   // own-warp Ps writes visible to own-warp PV reads

    // O += P V : own 16 rows x 64 dims; A = own Ps rows, B = Vs (shared).
    #pragma unroll
    for (int ks = 0; ks < 8; ks++) {
      int kb = ks * 8;
      uint32_t a[4], bb[8][2];
      a[0] = __float_as_uint(Ps[wrow * AW + kb + tig]);
      a[1] = __float_as_uint(Ps[(wrow + 8) * AW + kb + tig]);
      a[2] = __float_as_uint(Ps[wrow * AW + kb + tig + 4]);
      a[3] = __float_as_uint(Ps[(wrow + 8) * AW + kb + tig + 4]);
      #pragma unroll
      for (int nt = 0; nt < 8; nt++) {
        int c0 = nt * 8 + gid;
        bb[nt][0] = __float_as_uint(Vs[c0 * AW + kb + tig]);
        bb[nt][1] = __float_as_uint(Vs[c0 * AW + kb + tig + 4]);
      }
      #pragma unroll
      for (int nt = 0; nt < 8; nt++)
        mma_tf32(oacc[nt], a, bb[nt]);
    }
  }

  // Epilogue: O / l, store (own 16 rows).
  float* Ob = O + (size_t)b * SEQ * EMBED + h * HDIM;
  float inv0 = 1.f / lrun[0];
  float inv1 = 1.f / lrun[1];
  int r0 = q0 + wrow;
  #pragma unroll
  for (int nt = 0; nt < 8; nt++) {
    int col = nt * 8 + 2 * tig;
    float2 o0, o1;
    o0.x = oacc[nt][0] * inv0;
    o0.y = oacc[nt][1] * inv0;
    o1.x = oacc[nt][2] * inv1;
    o1.y = oacc[nt][3] * inv1;
    *(float2*)&Ob[(size_t)r0 * EMBED + col] = o0;
    *(float2*)&Ob[(size_t)(r0 + 8) * EMBED + col] = o1;
  }
}

// ---------------------------------------------------------------------------
extern "C" void kernel_launch(void* const* d_in, const int* in_sizes, int n_in,
                              void* d_out, int out_size) {
  (void)in_sizes; (void)n_in; (void)out_size;
  const float* q  = (const float*)d_in[0];
  const float* k  = (const float*)d_in[1];
  const float* v  = (const float*)d_in[2];
  // d_in[3] = mask (tril) — causal structure known, unused
  const float* Wq = (const float*)d_in[4];
  const float* bq = (const float*)d_in[5];
  const float* Wk = (const float*)d_in[6];
  const float* bk = (const float*)d_in[7];
  const float* Wv = (const float*)d_in[8];
  const float* bv = (const float*)d_in[9];
  const float* Wo = (const float*)d_in[10];
  const float* bo = (const float*)d_in[11];
  float* out = (float*)d_out;

  float *Qh, *Kh, *Vh, *Y, *Wt;
  cudaGetSymbolAddress((void**)&Qh, g_Qh);
  cudaGetSymbolAddress((void**)&Kh, g_Kh);
  cudaGetSymbolAddress((void**)&Vh, g_Vh);
  cudaGetSymbolAddress((void**)&Y,  g_Y);
  cudaGetSymbolAddress((void**)&Wt, g_Wt);

  transpose_w<<<dim3(32, 32, 4), dim3(32, 8)>>>(Wq, Wk, Wv, Wo, Wt);

  GemmArgs aq{q, Wt + 0*(size_t)EMBED*EMBED, bq, Qh};
  GemmArgs ak{k, Wt + 1*(size_t)EMBED*EMBED, bk, Kh};
  GemmArgs av{v, Wt + 2*(size_t)EMBED*EMBED, bv, Vh};
  gemm_mma<<<dim3(EMBED/128, MROWS/128, 3), 256>>>(aq, ak, av);

  const int attn_smem = 256 * AW * sizeof(float);  // 69632 B
  cudaFuncSetAttribute(attn_mma,
                       cudaFuncAttributeMaxDynamicSharedMemorySize, attn_smem);
  attn_mma<<<dim3(SEQ/128, BATCH*NHEAD), 256, attn_smem>>>(Qh, Kh, Vh, Y);

  GemmArgs ao{Y, Wt + 3*(size_t)EMBED*EMBED, bo, out};
  gemm_mma<<<dim3(EMBED/128, MROWS/128, 1), 256>>>(ao, ao, ao);
}